// round 1
// baseline (speedup 1.0000x reference)
#include <cuda_runtime.h>

#define BATCH 32
#define HH 512
#define WW 512
#define NPX (BATCH * HH * WW)

// 9x9 kernel weights, broadcast-uniform -> constant bank (LDC/LDCU path)
__constant__ float c_w[81];

// Scratch (device globals: allocation-free per harness rules)
__device__ float g_lm[NPX];
__device__ float g_s2[NPX];
__device__ float g_sig[NPX];
__device__ float g_part[BATCH * 256];
__device__ float g_msig[BATCH];

// ---------------------------------------------------------------------------
// Shared blur core: 32x32 output tile, block (32,4). Each thread: 1 col x 8
// rows. smem tile is 40x40 (halo 4). Lanes (tx) read consecutive smem words ->
// conflict-free. Per m-row j we load 9 values once and scatter into up to 8
// accumulators: 18 LDS/px, 81 FMA/px -> FMA-bound.
// Correlation (no flip), matching jax.lax.conv_general_dilated.
// ---------------------------------------------------------------------------
__device__ __forceinline__ void blur_tile(const float (*sm)[40], int tx, int tz,
                                          float acc[8]) {
#pragma unroll
    for (int i = 0; i < 8; i++) acc[i] = 0.f;
#pragma unroll
    for (int j = 0; j < 16; j++) {
        float v[9];
#pragma unroll
        for (int k = 0; k < 9; k++) v[k] = sm[8 * tz + j][tx + k];
#pragma unroll
        for (int ky = 0; ky < 9; ky++) {
            int oy = j - ky;
            if (oy >= 0 && oy < 8) {
#pragma unroll
                for (int k = 0; k < 9; k++)
                    acc[oy] = fmaf(c_w[ky * 9 + k], v[k], acc[oy]);
            }
        }
    }
}

// ---------------------------------------------------------------------------
// Stage 1: load x tile (40x40 px, 3ch), build m and q tiles in smem,
// blur m -> lm, compute s2 = q - 2*lm*m + lm^2. Write lm, s2.
// ---------------------------------------------------------------------------
__global__ __launch_bounds__(128) void k_stage1(const float* __restrict__ x) {
    __shared__ float sm[40][40];
    __shared__ float sq[40][40];

    const int b = blockIdx.z;
    const int x0 = blockIdx.x * 32, y0 = blockIdx.y * 32;
    const int tid = threadIdx.y * 32 + threadIdx.x;
    const float inv3 = 1.f / 3.f;

    for (int i = tid; i < 1600; i += 128) {
        int r = i / 40, c = i - r * 40;
        int gy = y0 - 4 + r, gx = x0 - 4 + c;
        float m = 0.f, q = 0.f;
        if ((unsigned)gy < (unsigned)HH && (unsigned)gx < (unsigned)WW) {
            const float* p = x + ((size_t)((b * HH + gy)) * WW + gx) * 3;
            float a0 = p[0], a1 = p[1], a2 = p[2];
            m = (a0 + a1 + a2) * inv3;
            q = (a0 * a0 + a1 * a1 + a2 * a2) * inv3;
        }
        sm[r][c] = m;
        sq[r][c] = q;
    }
    __syncthreads();

    const int tx = threadIdx.x, tz = threadIdx.y;
    float acc[8];
    blur_tile(sm, tx, tz, acc);

#pragma unroll
    for (int oy = 0; oy < 8; oy++) {
        float lm = acc[oy];
        float mc = sm[8 * tz + oy + 4][tx + 4];
        float qc = sq[8 * tz + oy + 4][tx + 4];
        // s2 = q - 2*lm*m + lm^2 = fma(lm, lm - 2m, q)
        float s2 = fmaf(lm, fmaf(-2.f, mc, lm), qc);
        int idx = (b * HH + y0 + 8 * tz + oy) * WW + x0 + tx;
        g_lm[idx] = lm;
        g_s2[idx] = fmaxf(s2, 0.f);
    }
}

// ---------------------------------------------------------------------------
// Stage 2: blur s2 -> sigma = sqrt(.), write sigma, and per-block partial sum
// of sigma into g_part (per-block slot: no atomics, graph-replay safe).
// ---------------------------------------------------------------------------
__global__ __launch_bounds__(128) void k_stage2() {
    __shared__ float ss[40][40];
    __shared__ float warpsum[4];

    const int b = blockIdx.z;
    const int x0 = blockIdx.x * 32, y0 = blockIdx.y * 32;
    const int tid = threadIdx.y * 32 + threadIdx.x;

    for (int i = tid; i < 1600; i += 128) {
        int r = i / 40, c = i - r * 40;
        int gy = y0 - 4 + r, gx = x0 - 4 + c;
        float s = 0.f;
        if ((unsigned)gy < (unsigned)HH && (unsigned)gx < (unsigned)WW)
            s = g_s2[(b * HH + gy) * WW + gx];
        ss[r][c] = s;
    }
    __syncthreads();

    const int tx = threadIdx.x, tz = threadIdx.y;
    float acc[8];
    blur_tile(ss, tx, tz, acc);

    float lsum = 0.f;
#pragma unroll
    for (int oy = 0; oy < 8; oy++) {
        float sig = sqrtf(fmaxf(acc[oy], 0.f));
        int idx = (b * HH + y0 + 8 * tz + oy) * WW + x0 + tx;
        g_sig[idx] = sig;
        lsum += sig;
    }

#pragma unroll
    for (int o = 16; o > 0; o >>= 1)
        lsum += __shfl_down_sync(0xFFFFFFFFu, lsum, o);
    if (tx == 0) warpsum[tz] = lsum;
    __syncthreads();
    if (tid == 0) {
        float t = warpsum[0] + warpsum[1] + warpsum[2] + warpsum[3];
        g_part[b * 256 + blockIdx.y * 16 + blockIdx.x] = t;
    }
}

// ---------------------------------------------------------------------------
// Stage 3: reduce 256 partials per batch -> mean_sigma[b]
// ---------------------------------------------------------------------------
__global__ void k_reduce() {
    __shared__ float ws[8];
    const int b = blockIdx.x;
    float v = g_part[b * 256 + threadIdx.x];
#pragma unroll
    for (int o = 16; o > 0; o >>= 1)
        v += __shfl_down_sync(0xFFFFFFFFu, v, o);
    if ((threadIdx.x & 31) == 0) ws[threadIdx.x >> 5] = v;
    __syncthreads();
    if (threadIdx.x == 0) {
        float t = 0.f;
#pragma unroll
        for (int i = 0; i < 8; i++) t += ws[i];
        g_msig[b] = t * (1.f / ((float)HH * (float)WW));
    }
}

// ---------------------------------------------------------------------------
// Stage 4: out = (x - lm) / max(mean_sigma[b], sigma). 4 px / thread,
// fully vectorized float4 traffic (DRAM-bound pass).
// ---------------------------------------------------------------------------
__global__ __launch_bounds__(256) void k_final(const float* __restrict__ x,
                                               float* __restrict__ out) {
    int t = blockIdx.x * 256 + threadIdx.x;
    int p = t * 4;
    if (p >= NPX) return;
    int b = p / (HH * WW);
    float ms = g_msig[b];

    float4 lm4 = *(const float4*)(g_lm + p);
    float4 sg4 = *(const float4*)(g_sig + p);
    const float4* xp = (const float4*)(x + (size_t)p * 3);
    float4 xa = xp[0], xb = xp[1], xc = xp[2];

    float lmv[4] = {lm4.x, lm4.y, lm4.z, lm4.w};
    float sgv[4] = {sg4.x, sg4.y, sg4.z, sg4.w};
    float inv[4];
#pragma unroll
    for (int i = 0; i < 4; i++) inv[i] = 1.f / fmaxf(ms, sgv[i]);

    float f[12] = {xa.x, xa.y, xa.z, xa.w, xb.x, xb.y,
                   xb.z, xb.w, xc.x, xc.y, xc.z, xc.w};
    float o[12];
#pragma unroll
    for (int j = 0; j < 12; j++) {
        int px = j / 3;
        o[j] = (f[j] - lmv[px]) * inv[px];
    }

    float4* op = (float4*)(out + (size_t)p * 3);
    op[0] = make_float4(o[0], o[1], o[2], o[3]);
    op[1] = make_float4(o[4], o[5], o[6], o[7]);
    op[2] = make_float4(o[8], o[9], o[10], o[11]);
}

// ---------------------------------------------------------------------------
extern "C" void kernel_launch(void* const* d_in, const int* in_sizes, int n_in,
                              void* d_out, int out_size) {
    const float* x = (const float*)d_in[0];

    // 9x9 kernel -> constant memory (capturable D2D async copy)
    cudaMemcpyToSymbolAsync(c_w, d_in[1], 81 * sizeof(float), 0,
                            cudaMemcpyDeviceToDevice, 0);

    dim3 blk(32, 4);
    dim3 grd(WW / 32, HH / 32, BATCH);
    k_stage1<<<grd, blk>>>(x);
    k_stage2<<<grd, blk>>>();
    k_reduce<<<BATCH, 256>>>();
    k_final<<<(NPX / 4 + 255) / 256, 256>>>(x, (float*)d_out);
}

// round 2
// speedup vs baseline: 1.1144x; 1.1144x over previous
#include <cuda_runtime.h>
#include <cstdint>

#define BATCH 32
#define HH 512
#define WW 512
#define NPX (BATCH * HH * WW)

#define TX 64  // output tile width
#define TY 32  // output tile height
#define SW 72  // smem tile width  (TX + 8)
#define SH 40  // smem tile height (TY + 8)

// 9x9 kernel weights in constant bank
__constant__ float c_w[81];

// Scratch (device globals: allocation-free per harness rules)
__device__ float g_lm[NPX];
__device__ float g_s2[NPX];
__device__ float g_sig[NPX];
__device__ float g_part[BATCH * 128];
__device__ float g_msig[BATCH];

typedef unsigned long long u64;

// --- f32x2 packed-math helpers (Blackwell FFMA2 path) ----------------------
__device__ __forceinline__ u64 bcast2(float w) {
    u64 r;
    asm("mov.b64 %0, {%1, %1};" : "=l"(r) : "r"(__float_as_uint(w)));
    return r;
}
__device__ __forceinline__ void fma2(u64& acc, u64 a, u64 b) {
    asm("fma.rn.f32x2 %0, %1, %2, %0;" : "+l"(acc) : "l"(a), "l"(b));
}
__device__ __forceinline__ u64 lds64(uint32_t a) {
    u64 v;
    asm volatile("ld.shared.b64 %0, [%1];" : "=l"(v) : "r"(a));
    return v;
}

// ---------------------------------------------------------------------------
// Blur core: block (32,4). Thread = 2 adjacent cols (2tx, 2tx+1) x 8 rows
// (8tz..8tz+7). Even taps read the aligned tile (sm), odd taps read the
// 1-element-shifted copy (smS) so every access is an aligned LDS.64.
// Outer k-loop rolled: 9 broadcast weight pairs live in regs per iteration
// (81 LDC total/thread instead of ~1150). acc[oy] is an f32x2 pair (colL,colR).
// ---------------------------------------------------------------------------
__device__ __forceinline__ void blur64(uint32_t smb, uint32_t smSb,
                                       int tx, int tz, u64 acc[8]) {
#pragma unroll
    for (int i = 0; i < 8; i++) acc[i] = 0ull;

#pragma unroll 1
    for (int k = 0; k < 9; k += 2) {  // even taps
        u64 w2[9];
#pragma unroll
        for (int ky = 0; ky < 9; ky++) w2[ky] = bcast2(c_w[ky * 9 + k]);
        uint32_t a0 = smb + (uint32_t)(((8 * tz) * SW + 2 * tx + k) * 4);
#pragma unroll
        for (int j = 0; j < 16; j++) {
            u64 pr = lds64(a0 + j * (SW * 4));
#pragma unroll
            for (int oy = 0; oy < 8; oy++) {
                int ky = j - oy;
                if (ky >= 0 && ky < 9) fma2(acc[oy], w2[ky], pr);
            }
        }
    }
#pragma unroll 1
    for (int k = 1; k < 9; k += 2) {  // odd taps via shifted copy
        u64 w2[9];
#pragma unroll
        for (int ky = 0; ky < 9; ky++) w2[ky] = bcast2(c_w[ky * 9 + k]);
        uint32_t a0 = smSb + (uint32_t)(((8 * tz) * SW + 2 * tx + (k - 1)) * 4);
#pragma unroll
        for (int j = 0; j < 16; j++) {
            u64 pr = lds64(a0 + j * (SW * 4));
#pragma unroll
            for (int oy = 0; oy < 8; oy++) {
                int ky = j - oy;
                if (ky >= 0 && ky < 9) fma2(acc[oy], w2[ky], pr);
            }
        }
    }
}

// ---------------------------------------------------------------------------
// Stage 1: load x tile (SHxSW px, 3ch), build m (aligned + shifted) and q
// tiles, blur m -> lm, s2 = q - 2*lm*m + lm^2. Write lm, s2 as float2.
// ---------------------------------------------------------------------------
__global__ __launch_bounds__(128) void k_stage1(const float* __restrict__ x) {
    __shared__ __align__(16) float sm[SH][SW];
    __shared__ __align__(16) float smS[SH][SW];
    __shared__ __align__(16) float sq[SH][SW];

    const int b = blockIdx.z;
    const int x0 = blockIdx.x * TX, y0 = blockIdx.y * TY;
    const int tid = threadIdx.y * 32 + threadIdx.x;
    const float inv3 = 1.f / 3.f;

    for (int i = tid; i < SH * SW; i += 128) {
        int r = i / SW, c = i - r * SW;
        int gy = y0 - 4 + r, gx = x0 - 4 + c;
        float m = 0.f, q = 0.f;
        if ((unsigned)gy < (unsigned)HH && (unsigned)gx < (unsigned)WW) {
            const float* p = x + ((size_t)(b * HH + gy) * WW + gx) * 3;
            float a0 = p[0], a1 = p[1], a2 = p[2];
            m = (a0 + a1 + a2) * inv3;
            q = fmaf(a0, a0, fmaf(a1, a1, a2 * a2)) * inv3;
        }
        sm[r][c] = m;
        sq[r][c] = q;
        if (c > 0) smS[r][c - 1] = m;
    }
    __syncthreads();

    const int tx = threadIdx.x, tz = threadIdx.y;
    uint32_t smb = (uint32_t)__cvta_generic_to_shared(&sm[0][0]);
    uint32_t smSb = (uint32_t)__cvta_generic_to_shared(&smS[0][0]);
    u64 acc[8];
    blur64(smb, smSb, tx, tz, acc);

#pragma unroll
    for (int oy = 0; oy < 8; oy++) {
        float lm0 = __uint_as_float((uint32_t)acc[oy]);
        float lm1 = __uint_as_float((uint32_t)(acc[oy] >> 32));
        int sr = 8 * tz + oy + 4;
        int sc = 2 * tx + 4;
        float m0 = sm[sr][sc], m1 = sm[sr][sc + 1];
        float q0 = sq[sr][sc], q1 = sq[sr][sc + 1];
        // s2 = q - 2*lm*m + lm^2 = fma(lm, lm - 2m, q)
        float s20 = fmaf(lm0, fmaf(-2.f, m0, lm0), q0);
        float s21 = fmaf(lm1, fmaf(-2.f, m1, lm1), q1);
        int idx = (b * HH + y0 + 8 * tz + oy) * WW + x0 + 2 * tx;
        *(float2*)&g_lm[idx] = make_float2(lm0, lm1);
        *(float2*)&g_s2[idx] = make_float2(fmaxf(s20, 0.f), fmaxf(s21, 0.f));
    }
}

// ---------------------------------------------------------------------------
// Stage 2: blur s2 -> sigma = sqrt(.), write sigma + per-block partial sums.
// ---------------------------------------------------------------------------
__global__ __launch_bounds__(128) void k_stage2() {
    __shared__ __align__(16) float ss[SH][SW];
    __shared__ __align__(16) float ssS[SH][SW];
    __shared__ float warpsum[4];

    const int b = blockIdx.z;
    const int x0 = blockIdx.x * TX, y0 = blockIdx.y * TY;
    const int tid = threadIdx.y * 32 + threadIdx.x;

    for (int i = tid; i < SH * SW; i += 128) {
        int r = i / SW, c = i - r * SW;
        int gy = y0 - 4 + r, gx = x0 - 4 + c;
        float s = 0.f;
        if ((unsigned)gy < (unsigned)HH && (unsigned)gx < (unsigned)WW)
            s = g_s2[(b * HH + gy) * WW + gx];
        ss[r][c] = s;
        if (c > 0) ssS[r][c - 1] = s;
    }
    __syncthreads();

    const int tx = threadIdx.x, tz = threadIdx.y;
    uint32_t smb = (uint32_t)__cvta_generic_to_shared(&ss[0][0]);
    uint32_t smSb = (uint32_t)__cvta_generic_to_shared(&ssS[0][0]);
    u64 acc[8];
    blur64(smb, smSb, tx, tz, acc);

    float lsum = 0.f;
#pragma unroll
    for (int oy = 0; oy < 8; oy++) {
        float s0 = sqrtf(fmaxf(__uint_as_float((uint32_t)acc[oy]), 0.f));
        float s1 = sqrtf(fmaxf(__uint_as_float((uint32_t)(acc[oy] >> 32)), 0.f));
        int idx = (b * HH + y0 + 8 * tz + oy) * WW + x0 + 2 * tx;
        *(float2*)&g_sig[idx] = make_float2(s0, s1);
        lsum += s0 + s1;
    }

#pragma unroll
    for (int o = 16; o > 0; o >>= 1)
        lsum += __shfl_down_sync(0xFFFFFFFFu, lsum, o);
    if (tx == 0) warpsum[tz] = lsum;
    __syncthreads();
    if (tid == 0) {
        float t = warpsum[0] + warpsum[1] + warpsum[2] + warpsum[3];
        g_part[b * 128 + blockIdx.y * 8 + blockIdx.x] = t;
    }
}

// ---------------------------------------------------------------------------
// Stage 3: reduce 128 partials per batch -> mean_sigma[b]
// ---------------------------------------------------------------------------
__global__ void k_reduce() {
    __shared__ float ws[4];
    const int b = blockIdx.x;
    float v = g_part[b * 128 + threadIdx.x];
#pragma unroll
    for (int o = 16; o > 0; o >>= 1)
        v += __shfl_down_sync(0xFFFFFFFFu, v, o);
    if ((threadIdx.x & 31) == 0) ws[threadIdx.x >> 5] = v;
    __syncthreads();
    if (threadIdx.x == 0) {
        float t = ws[0] + ws[1] + ws[2] + ws[3];
        g_msig[b] = t * (1.f / ((float)HH * (float)WW));
    }
}

// ---------------------------------------------------------------------------
// Stage 4: out = (x - lm) / max(mean_sigma[b], sigma). 4 px / thread,
// float4 traffic (DRAM-bound pass, ~71% of peak).
// ---------------------------------------------------------------------------
__global__ __launch_bounds__(256) void k_final(const float* __restrict__ x,
                                               float* __restrict__ out) {
    int t = blockIdx.x * 256 + threadIdx.x;
    int p = t * 4;
    if (p >= NPX) return;
    int b = p / (HH * WW);
    float ms = g_msig[b];

    float4 lm4 = *(const float4*)(g_lm + p);
    float4 sg4 = *(const float4*)(g_sig + p);
    const float4* xp = (const float4*)(x + (size_t)p * 3);
    float4 xa = xp[0], xb = xp[1], xc = xp[2];

    float lmv[4] = {lm4.x, lm4.y, lm4.z, lm4.w};
    float sgv[4] = {sg4.x, sg4.y, sg4.z, sg4.w};
    float inv[4];
#pragma unroll
    for (int i = 0; i < 4; i++) inv[i] = 1.f / fmaxf(ms, sgv[i]);

    float f[12] = {xa.x, xa.y, xa.z, xa.w, xb.x, xb.y,
                   xb.z, xb.w, xc.x, xc.y, xc.z, xc.w};
    float o[12];
#pragma unroll
    for (int j = 0; j < 12; j++) {
        int px = j / 3;
        o[j] = (f[j] - lmv[px]) * inv[px];
    }

    float4* op = (float4*)(out + (size_t)p * 3);
    op[0] = make_float4(o[0], o[1], o[2], o[3]);
    op[1] = make_float4(o[4], o[5], o[6], o[7]);
    op[2] = make_float4(o[8], o[9], o[10], o[11]);
}

// ---------------------------------------------------------------------------
extern "C" void kernel_launch(void* const* d_in, const int* in_sizes, int n_in,
                              void* d_out, int out_size) {
    const float* x = (const float*)d_in[0];

    cudaMemcpyToSymbolAsync(c_w, d_in[1], 81 * sizeof(float), 0,
                            cudaMemcpyDeviceToDevice, 0);

    dim3 blk(32, 4);
    dim3 grd(WW / TX, HH / TY, BATCH);
    k_stage1<<<grd, blk>>>(x);
    k_stage2<<<grd, blk>>>();
    k_reduce<<<BATCH, 128>>>();
    k_final<<<(NPX / 4 + 255) / 256, 256>>>(x, (float*)d_out);
}

// round 3
// speedup vs baseline: 1.1864x; 1.0646x over previous
#include <cuda_runtime.h>
#include <cuda_fp16.h>
#include <cstdint>

#define BATCH 32
#define HH 512
#define WW 512
#define NPX (BATCH * HH * WW)

#define TX 64  // output tile width
#define TY 64  // output tile height
#define SW 72  // smem tile width  (TX + 8)
#define SH 72  // smem tile height (TY + 8)

// 9x9 kernel weights in constant bank
__constant__ float c_w[81];

// Scratch (device globals: allocation-free per harness rules)
__device__ __half g_lm[NPX];   // local mean, fp16 (|lm| < 1, abs err ~1.5e-5)
__device__ __half g_s2[NPX];   // channel-mean squared-dev, fp16 (rel err ~2.4e-4)
__device__ float  g_sig[NPX];  // sigma, fp32 (feeds max() denominator)
__device__ float  g_part[BATCH * 64];
__device__ float  g_msig[BATCH];

typedef unsigned long long u64;

// --- f32x2 packed-math helpers (Blackwell FFMA2 path) ----------------------
__device__ __forceinline__ u64 bcast2(float w) {
    u64 r;
    asm("mov.b64 %0, {%1, %1};" : "=l"(r) : "r"(__float_as_uint(w)));
    return r;
}
__device__ __forceinline__ void fma2(u64& acc, u64 a, u64 b) {
    asm("fma.rn.f32x2 %0, %1, %2, %0;" : "+l"(acc) : "l"(a), "l"(b));
}
__device__ __forceinline__ u64 lds64(uint32_t a) {
    u64 v;
    asm volatile("ld.shared.b64 %0, [%1];" : "=l"(v) : "r"(a));
    return v;
}

// ---------------------------------------------------------------------------
// Blur core: block (32,8). Thread = 2 adjacent cols (2tx, 2tx+1) x 8 rows
// (8tz..8tz+7). Even taps read the aligned tile, odd taps the 1-element-
// shifted copy -> every access is an aligned LDS.64, conflict-free (lanes =
// consecutive 8B). Outer k-loop rolled: 9 broadcast weight pairs in regs per
// iteration (81 LDC total/thread). acc[oy] = f32x2 pair (colL, colR).
// ---------------------------------------------------------------------------
__device__ __forceinline__ void blur64(uint32_t smb, uint32_t smSb,
                                       int tx, int tz, u64 acc[8]) {
#pragma unroll
    for (int i = 0; i < 8; i++) acc[i] = 0ull;

#pragma unroll 1
    for (int k = 0; k < 9; k += 2) {  // even taps
        u64 w2[9];
#pragma unroll
        for (int ky = 0; ky < 9; ky++) w2[ky] = bcast2(c_w[ky * 9 + k]);
        uint32_t a0 = smb + (uint32_t)(((8 * tz) * SW + 2 * tx + k) * 4);
#pragma unroll
        for (int j = 0; j < 16; j++) {
            u64 pr = lds64(a0 + j * (SW * 4));
#pragma unroll
            for (int oy = 0; oy < 8; oy++) {
                int ky = j - oy;
                if (ky >= 0 && ky < 9) fma2(acc[oy], w2[ky], pr);
            }
        }
    }
#pragma unroll 1
    for (int k = 1; k < 9; k += 2) {  // odd taps via shifted copy
        u64 w2[9];
#pragma unroll
        for (int ky = 0; ky < 9; ky++) w2[ky] = bcast2(c_w[ky * 9 + k]);
        uint32_t a0 = smSb + (uint32_t)(((8 * tz) * SW + 2 * tx + (k - 1)) * 4);
#pragma unroll
        for (int j = 0; j < 16; j++) {
            u64 pr = lds64(a0 + j * (SW * 4));
#pragma unroll
            for (int oy = 0; oy < 8; oy++) {
                int ky = j - oy;
                if (ky >= 0 && ky < 9) fma2(acc[oy], w2[ky], pr);
            }
        }
    }
}

// ---------------------------------------------------------------------------
// Stage 1: load x tile (72x72 px, 3ch), build m (aligned + shifted) and q
// tiles, blur m -> lm, s2 = q - 2*lm*m + lm^2. Write lm, s2 as half2.
// Dynamic smem: 3 arrays of 72*72 floats = 62208 B.
// ---------------------------------------------------------------------------
__global__ __launch_bounds__(256) void k_stage1(const float* __restrict__ x) {
    extern __shared__ float dsm[];
    float* sm  = dsm;                 // [SH][SW]
    float* smS = dsm + SH * SW;       // shifted copy
    float* sq  = dsm + 2 * SH * SW;   // mean of squares

    const int b = blockIdx.z;
    const int x0 = blockIdx.x * TX, y0 = blockIdx.y * TY;
    const int tid = threadIdx.y * 32 + threadIdx.x;
    const float inv3 = 1.f / 3.f;

    for (int i = tid; i < SH * SW; i += 256) {
        int r = i / SW, c = i - r * SW;
        int gy = y0 - 4 + r, gx = x0 - 4 + c;
        float m = 0.f, q = 0.f;
        if ((unsigned)gy < (unsigned)HH && (unsigned)gx < (unsigned)WW) {
            const float* p = x + ((size_t)(b * HH + gy) * WW + gx) * 3;
            float a0 = __ldcs(p), a1 = __ldcs(p + 1), a2 = __ldcs(p + 2);
            m = (a0 + a1 + a2) * inv3;
            q = fmaf(a0, a0, fmaf(a1, a1, a2 * a2)) * inv3;
        }
        sm[i] = m;
        sq[i] = q;
        if (c > 0) smS[i - 1] = m;
    }
    __syncthreads();

    const int tx = threadIdx.x, tz = threadIdx.y;
    uint32_t smb  = (uint32_t)__cvta_generic_to_shared(sm);
    uint32_t smSb = (uint32_t)__cvta_generic_to_shared(smS);
    u64 acc[8];
    blur64(smb, smSb, tx, tz, acc);

#pragma unroll
    for (int oy = 0; oy < 8; oy++) {
        float lm0 = __uint_as_float((uint32_t)acc[oy]);
        float lm1 = __uint_as_float((uint32_t)(acc[oy] >> 32));
        int si = (8 * tz + oy + 4) * SW + 2 * tx + 4;
        float m0 = sm[si], m1 = sm[si + 1];
        float q0 = sq[si], q1 = sq[si + 1];
        // s2 = q - 2*lm*m + lm^2 = fma(lm, lm - 2m, q)
        float s20 = fmaxf(fmaf(lm0, fmaf(-2.f, m0, lm0), q0), 0.f);
        float s21 = fmaxf(fmaf(lm1, fmaf(-2.f, m1, lm1), q1), 0.f);
        int idx = (b * HH + y0 + 8 * tz + oy) * WW + x0 + 2 * tx;
        *(__half2*)&g_lm[idx] = __floats2half2_rn(lm0, lm1);
        *(__half2*)&g_s2[idx] = __floats2half2_rn(s20, s21);
    }
}

// ---------------------------------------------------------------------------
// Stage 2: blur s2 -> sigma = sqrt(.), write sigma + per-block partial sums.
// Static smem: 2 arrays (40.5 KB).
// ---------------------------------------------------------------------------
__global__ __launch_bounds__(256) void k_stage2() {
    __shared__ __align__(16) float ss[SH][SW];
    __shared__ __align__(16) float ssS[SH][SW];
    __shared__ float warpsum[8];

    const int b = blockIdx.z;
    const int x0 = blockIdx.x * TX, y0 = blockIdx.y * TY;
    const int tid = threadIdx.y * 32 + threadIdx.x;

    for (int i = tid; i < SH * SW; i += 256) {
        int r = i / SW, c = i - r * SW;
        int gy = y0 - 4 + r, gx = x0 - 4 + c;
        float s = 0.f;
        if ((unsigned)gy < (unsigned)HH && (unsigned)gx < (unsigned)WW)
            s = __half2float(g_s2[(b * HH + gy) * WW + gx]);
        ss[r][c] = s;
        if (c > 0) ssS[r][c - 1] = s;
    }
    __syncthreads();

    const int tx = threadIdx.x, tz = threadIdx.y;
    uint32_t smb  = (uint32_t)__cvta_generic_to_shared(&ss[0][0]);
    uint32_t smSb = (uint32_t)__cvta_generic_to_shared(&ssS[0][0]);
    u64 acc[8];
    blur64(smb, smSb, tx, tz, acc);

    float lsum = 0.f;
#pragma unroll
    for (int oy = 0; oy < 8; oy++) {
        float s0 = sqrtf(fmaxf(__uint_as_float((uint32_t)acc[oy]), 0.f));
        float s1 = sqrtf(fmaxf(__uint_as_float((uint32_t)(acc[oy] >> 32)), 0.f));
        int idx = (b * HH + y0 + 8 * tz + oy) * WW + x0 + 2 * tx;
        *(float2*)&g_sig[idx] = make_float2(s0, s1);
        lsum += s0 + s1;
    }

#pragma unroll
    for (int o = 16; o > 0; o >>= 1)
        lsum += __shfl_down_sync(0xFFFFFFFFu, lsum, o);
    if (tx == 0) warpsum[tz] = lsum;
    __syncthreads();
    if (tid == 0) {
        float t = 0.f;
#pragma unroll
        for (int i = 0; i < 8; i++) t += warpsum[i];
        g_part[b * 64 + blockIdx.y * 8 + blockIdx.x] = t;
    }
}

// ---------------------------------------------------------------------------
// Stage 3: reduce 64 partials per batch -> mean_sigma[b]
// ---------------------------------------------------------------------------
__global__ void k_reduce() {
    __shared__ float ws[2];
    const int b = blockIdx.x;
    float v = g_part[b * 64 + threadIdx.x];
#pragma unroll
    for (int o = 16; o > 0; o >>= 1)
        v += __shfl_down_sync(0xFFFFFFFFu, v, o);
    if ((threadIdx.x & 31) == 0) ws[threadIdx.x >> 5] = v;
    __syncthreads();
    if (threadIdx.x == 0)
        g_msig[b] = (ws[0] + ws[1]) * (1.f / ((float)HH * (float)WW));
}

// ---------------------------------------------------------------------------
// Stage 4: out = (x - lm) / max(mean_sigma[b], sigma). 4 px / thread,
// streaming loads/stores (data touched once).
// ---------------------------------------------------------------------------
__global__ __launch_bounds__(256) void k_final(const float* __restrict__ x,
                                               float* __restrict__ out) {
    int t = blockIdx.x * 256 + threadIdx.x;
    int p = t * 4;
    if (p >= NPX) return;
    int b = p / (HH * WW);
    float ms = g_msig[b];

    uint2 lmu = __ldcs((const uint2*)((const __half*)g_lm + p));
    __half2 l01 = *reinterpret_cast<__half2*>(&lmu.x);
    __half2 l23 = *reinterpret_cast<__half2*>(&lmu.y);
    float4 sg4 = __ldcs((const float4*)(g_sig + p));
    const float4* xp = (const float4*)(x + (size_t)p * 3);
    float4 xa = __ldcs(xp), xb = __ldcs(xp + 1), xc = __ldcs(xp + 2);

    float lmv[4] = {__low2float(l01), __high2float(l01),
                    __low2float(l23), __high2float(l23)};
    float sgv[4] = {sg4.x, sg4.y, sg4.z, sg4.w};
    float inv[4];
#pragma unroll
    for (int i = 0; i < 4; i++) inv[i] = 1.f / fmaxf(ms, sgv[i]);

    float f[12] = {xa.x, xa.y, xa.z, xa.w, xb.x, xb.y,
                   xb.z, xb.w, xc.x, xc.y, xc.z, xc.w};
    float o[12];
#pragma unroll
    for (int j = 0; j < 12; j++) {
        int px = j / 3;
        o[j] = (f[j] - lmv[px]) * inv[px];
    }

    float4* op = (float4*)(out + (size_t)p * 3);
    __stcs(op,     make_float4(o[0], o[1], o[2],  o[3]));
    __stcs(op + 1, make_float4(o[4], o[5], o[6],  o[7]));
    __stcs(op + 2, make_float4(o[8], o[9], o[10], o[11]));
}

// ---------------------------------------------------------------------------
extern "C" void kernel_launch(void* const* d_in, const int* in_sizes, int n_in,
                              void* d_out, int out_size) {
    const float* x = (const float*)d_in[0];

    cudaMemcpyToSymbolAsync(c_w, d_in[1], 81 * sizeof(float), 0,
                            cudaMemcpyDeviceToDevice, 0);

    const int smem1 = 3 * SH * SW * (int)sizeof(float);  // 62208 B
    cudaFuncSetAttribute(k_stage1, cudaFuncAttributeMaxDynamicSharedMemorySize,
                         smem1);

    dim3 blk(32, 8);
    dim3 grd(WW / TX, HH / TY, BATCH);
    k_stage1<<<grd, blk, smem1>>>(x);
    k_stage2<<<grd, blk>>>();
    k_reduce<<<BATCH, 64>>>();
    k_final<<<(NPX / 4 + 255) / 256, 256>>>(x, (float*)d_out);
}